// round 16
// baseline (speedup 1.0000x reference)
#include <cuda_runtime.h>
#include <cstddef>

#define B_   16
#define CO_  64
#define N_   128
#define HW_  16384
#define MODES_ 400
#define BC_  1024
#define BO_  1024
#define NC_  73
#define NK_  65
#define PS_  (N_*NK_)      // 8320
#define FW_SMEM  76800     // k_fwd dynamic smem -> 3 blocks/SM
#define IW_SMEM  52640     // k_invwh dynamic smem
#define WT_SMEM  51328     // k_wt dynamic smem

typedef unsigned long long u64;
__device__ __forceinline__ u64 pack2(float lo, float hi) {
    u64 r; asm("mov.b64 %0, {%1,%2};" : "=l"(r) : "f"(lo), "f"(hi)); return r;
}
__device__ __forceinline__ float2 unpack2(u64 v) {
    float2 f; asm("mov.b64 {%0,%1}, %2;" : "=f"(f.x), "=f"(f.y) : "l"(v)); return f;
}
__device__ __forceinline__ u64 fma2(u64 a, u64 b, u64 c) {
    u64 d; asm("fma.rn.f32x2 %0, %1, %2, %3;" : "=l"(d) : "l"(a), "l"(b), "l"(c)); return d;
}

__device__ float  g_Xh[(size_t)MODES_*BC_];    // [mode][bc]
__device__ float  g_Z [(size_t)MODES_*BO_];    // [mode][bo]
__device__ float2 g_W2[(size_t)MODES_*4096];   // [mode][i] = (Wp, Wm)
__device__ float  g_buf1[(size_t)BO_*PS_];

__constant__ float GK[9] = {
    1.3383062e-04f, 4.4318606e-03f, 5.3991128e-02f, 2.4197145e-01f,
    3.9894348e-01f, 2.4197145e-01f, 5.3991128e-02f, 4.4318606e-03f,
    1.3383062e-04f
};

__device__ __forceinline__ void fill_tabs_n(float* ct, float* st, int nthr) {
    const float w = 6.283185307179586f / 128.0f;
    for (int t = threadIdx.x; t < 128; t += nthr) {
        float s, c;
        sincosf(w * (float)t, &s, &c);
        ct[t] = c; st[t] = s;
    }
}

// ---------------------------------------------------------------------------
// K0: transpose + fold weights once: g_W2[m][i] = (0.5(w+wn), 0.5(w-wn))
// ---------------------------------------------------------------------------
__global__ void __launch_bounds__(256) k_wt(const float* __restrict__ w1) {
    extern __shared__ float ws[];            // [32][401]
    int i0 = blockIdx.x * 32;
    for (int idx = threadIdx.x; idx < 32*400; idx += 256) {
        int r = idx / 400, m = idx - r*400;
        ws[r*401 + m] = w1[(size_t)(i0 + r)*400 + m];
    }
    __syncthreads();
    for (int idx = threadIdx.x; idx < 12800; idx += 256) {
        int m = idx >> 5, r = idx & 31;
        int m1 = m / 20, m2 = m - m1*20;
        int mn = ((20 - m1) % 20) * 20 + ((20 - m2) % 20);
        float w  = ws[r*401 + m];
        float wn = ws[r*401 + mn];
        g_W2[(size_t)m*4096 + i0 + r] = make_float2(0.5f*(w+wn), 0.5f*(w-wn));
    }
}

// ---------------------------------------------------------------------------
// K1: forward truncated DHT (packed f32x2), 76.8KB smem -> 3 blocks/SM.
// ---------------------------------------------------------------------------
__global__ void __launch_bounds__(320, 3) k_fwd(const float* __restrict__ x) {
    extern __shared__ float sm[];
    float* CT = sm;             // 64*20
    float* ST = sm + 1280;      // 64*20
    float* xp = sm + 2560;      // 128*65
    float* xm = xp + 8320;      // 128*65
    float* U  = xp;             // overlay after GEMM (2560)
    float* V  = xp + 2560;      // (2560)
    float2* FF = (float2*)(xp + 5120);   // [64][20] pairs
    float2* TT = (float2*)xm;            // [20][65] pairs

    int tid = threadIdx.x;
    int bc  = blockIdx.x;
    const float* xb = x + (size_t)bc * HW_;
    const float wg = 6.283185307179586f / 128.0f;

    for (int idx = tid; idx < 1280; idx += 320) {
        int q = idx / 20, k2 = idx - q*20;
        if (q == 0) { CT[idx] = 1.f; ST[idx] = 0.f; }
        else {
            int t = (q * k2) & 127;
            float s, c; sincosf(wg * (float)t, &s, &c);
            CT[idx] = c; ST[idx] = s;
        }
    }
    for (int idx = tid; idx < 8192; idx += 320) {
        int r = idx >> 6, q = idx & 63;
        const float* row = xb + r * 128;
        if (q == 0) { xp[r*65] = row[0]; xm[r*65] = row[64]; }
        else {
            float a = row[q], b = row[128 - q];
            xp[r*65 + q] = a + b; xm[r*65 + q] = a - b;
        }
    }
    __syncthreads();

    int ty = tid & 31, tx = tid >> 5;
    int isU = (tx < 5);
    int c0  = (isU ? tx : tx - 5) * 4;
    {
        const float* A  = isU ? xp : xm;
        const float* Bm = isU ? CT : ST;
        u64 z = pack2(0.f, 0.f);
        u64 acc01[4] = {z,z,z,z}, acc23[4] = {z,z,z,z};
        float pm[4];
#pragma unroll
        for (int i = 0; i < 4; ++i)
            pm[i] = isU ? xm[(ty + 32*i)*65] : 0.f;
#pragma unroll 4
        for (int q = 0; q < 64; ++q) {
            u64 b01 = *(const u64*)(Bm + q*20 + c0);
            u64 b23 = *(const u64*)(Bm + q*20 + c0 + 2);
#pragma unroll
            for (int i = 0; i < 4; ++i) {
                float a = A[(ty + 32*i)*65 + q];
                u64 aa = pack2(a, a);
                acc01[i] = fma2(aa, b01, acc01[i]);
                acc23[i] = fma2(aa, b23, acc23[i]);
            }
        }
        __syncthreads();
        float* O = isU ? U : V;
#pragma unroll
        for (int i = 0; i < 4; ++i) {
            float2 f01 = unpack2(acc01[i]);
            float2 f23 = unpack2(acc23[i]);
            float* o = O + (ty + 32*i)*20 + c0;
            o[0] = f01.x + pm[i]; o[1] = f01.y - pm[i];
            o[2] = f23.x + pm[i]; o[3] = f23.y - pm[i];
        }
    }
    __syncthreads();

    for (int idx = tid; idx < 1280; idx += 320) {
        int n = idx / 20, k2 = idx - n*20;
        float cd = CT[20 + k2], sd = ST[20 + k2];
        float f1, f2;
        if (n == 0) {
            f1 = U[0*20+k2]  - (sd*U[127*20+k2] + cd*V[127*20+k2]);
            f2 = U[64*20+k2] - (sd*U[63*20+k2]  + cd*V[63*20+k2]);
        } else {
            int nm = n - 1, nn = 128 - n, nnm = 127 - n;
            float e1a = U[n*20+k2]  - (sd*U[nm*20+k2]  + cd*V[nm*20+k2]);
            float e2a = V[n*20+k2]  + (cd*U[nm*20+k2]  - sd*V[nm*20+k2]);
            float e1b = U[nn*20+k2] - (sd*U[nnm*20+k2] + cd*V[nnm*20+k2]);
            float e2b = V[nn*20+k2] + (cd*U[nnm*20+k2] - sd*V[nnm*20+k2]);
            f1 = e1a + e1b;
            f2 = e2a - e2b;
        }
        FF[n*20 + k2] = make_float2(f1, f2);
    }
    for (int idx = tid; idx < 1300; idx += 320) {
        int k1 = idx / 65, n = idx - k1*65;
        if (n == 0) TT[idx] = make_float2(1.f, (k1 & 1) ? -1.f : 1.f);
        else if (n < 64) {
            int t = (k1*n) & 127;
            float s, c; sincosf(wg * (float)t, &s, &c);
            TT[idx] = make_float2(c, -s);
        }
    }
    __syncthreads();

    {
        const u64* TT64 = (const u64*)TT;
        const u64* FF64 = (const u64*)FF;
        for (int o = tid; o < 400; o += 320) {
            int k1 = o % 20, k2 = o / 20;
            u64 acc2 = pack2(0.f, 0.f);
#pragma unroll 8
            for (int n = 0; n < 64; ++n)
                acc2 = fma2(TT64[k1*65 + n], FF64[n*20 + k2], acc2);
            float2 f = unpack2(acc2);
            g_Xh[(size_t)(k1*20 + k2)*BC_ + bc] = f.x + f.y;
        }
    }
}

// ---------------------------------------------------------------------------
// K2: folded compl_mul2d, split by o-quarter: grid = 400 modes x 4 quarters.
// Each block: 8KB X + 8KB W-quarter = 16KB smem -> ~8 blocks/SM resident.
// ---------------------------------------------------------------------------
__global__ void __launch_bounds__(256) k_mul(void) {
    __shared__ __align__(16) float X2[2048];   // [b*128 + i*2] = (X, Xneg)
    __shared__ __align__(16) float W2[2048];   // [i*32 + oo*2] = (Wp, Wm), 16 oo
    int m    = blockIdx.x >> 2;
    int quad = blockIdx.x & 3;
    int m1 = m / 20, m2 = m % 20;
    int mn = ((20 - m1) % 20) * 20 + ((20 - m2) % 20);

    for (int i = threadIdx.x; i < 1024; i += 256) {
        X2[i*2]     = g_Xh[(size_t)m  * BC_ + i];
        X2[i*2 + 1] = g_Xh[(size_t)mn * BC_ + i];
    }
    for (int idx = threadIdx.x; idx < 1024; idx += 256) {
        int i = idx >> 4, oo = idx & 15;
        ((float2*)W2)[i*16 + oo] =
            g_W2[(size_t)m*4096 + i*64 + quad*16 + oo];
    }
    __syncthreads();

    {
        int p = threadIdx.x;            // 256 outputs: 16 b x 16 oo
        int b = p >> 4, oo = p & 15;
        const u64* x2 = (const u64*)X2 + b*64;
        const u64* w2 = (const u64*)W2 + oo;
        u64 acc2 = pack2(0.f, 0.f);
#pragma unroll 8
        for (int i = 0; i < 64; ++i)
            acc2 = fma2(x2[i], w2[i*16], acc2);
        float2 f = unpack2(acc2);
        g_Z[(size_t)m * BO_ + b*64 + quad*16 + oo] = f.x + f.y;
    }
}

// ---------------------------------------------------------------------------
// K3: FUSED inverse transform + W-blur(+mask) + H-blur. One block per (b,o).
// ---------------------------------------------------------------------------
__global__ void __launch_bounds__(256) k_invwh(void) {
    extern __shared__ float sm[];
    float*  ct = sm;
    float*  st = sm + 128;
    float*  Zs = sm + 256;              // [20][21] padded
    float2* AB = (float2*)(sm + 676);   // [21][73] pairs (A,B)
    float*  pl = sm + 3742;             // stride 129, 73 cols
    float*  G1 = pl;
    float*  G2 = pl + 1460;
    float*  P1 = pl + 2920;
    float*  P2 = pl + 4380;

    int tid = threadIdx.x;
    int bo  = blockIdx.x;
    fill_tabs_n(ct, st, 256);
    for (int i = tid; i < 400; i += 256) {
        int m1 = i / 20, m2 = i - m1*20;
        Zs[m1*21 + m2] = g_Z[(size_t)i * BO_ + bo];
    }
    __syncthreads();

    // phase A: m1-register-tiled (4 per thread)
    const float inv = 6.103515625e-05f;
    for (int task = tid; task < 365; task += 256) {
        int j = task / 5, g = task - j*5;
        int m1b = g * 4;
        int n2 = (j < 37) ? j : j + 55;
        float a0=0.f,a1=0.f,a2=0.f,a3=0.f;
        float b0=0.f,b1=0.f,b2=0.f,b3=0.f;
        int t = 0;
#pragma unroll
        for (int m2 = 0; m2 < 20; ++m2) {
            float c = ct[t], s = st[t];
            float z0 = Zs[(m1b+0)*21 + m2];
            float z1 = Zs[(m1b+1)*21 + m2];
            float z2 = Zs[(m1b+2)*21 + m2];
            float z3 = Zs[(m1b+3)*21 + m2];
            a0 += z0*c; b0 += z0*s;
            a1 += z1*c; b1 += z1*s;
            a2 += z2*c; b2 += z2*s;
            a3 += z3*c; b3 += z3*s;
            t = (t + n2) & 127;
        }
        float cb = ct[n2], sb = st[n2];
        float ga[4] = {a0*inv, a1*inv, a2*inv, a3*inv};
        float gb[4] = {b0*inv, b1*inv, b2*inv, b3*inv};
#pragma unroll
        for (int u = 0; u < 4; ++u) {
            int m1 = m1b + u;
            G1[m1*73+j] = ga[u]; G2[m1*73+j] = gb[u];
            P1[m1*73+j] = cb*ga[u] - sb*gb[u];
            P2[m1*73+j] = sb*ga[u] + cb*gb[u];
        }
    }
    __syncthreads();

    for (int idx = tid; idx < 1533; idx += 256) {
        int m = idx / 73, j = idx - m*73;
        float a = 0.f, b = 0.f;
        if (m < 20) { a = G1[m*73+j]; b = G2[m*73+j]; }
        if (m > 0)  { a -= P2[(m-1)*73+j]; b += P1[(m-1)*73+j]; }
        AB[idx] = make_float2(a, b);
    }
    __syncthreads();

    // stage2: one warp per j, lane covers n1=l and n1=l+32
    {
        int l = tid & 31, w = tid >> 5;
        u64 cs[21];
#pragma unroll
        for (int m = 0; m < 21; ++m) {
            int tt = (l * m) & 127;
            cs[m] = pack2(ct[tt], st[tt]);
        }
        const u64* AB64 = (const u64*)AB;
        for (int j = w; j < 73; j += 8) {
            u64 z = pack2(0.f, 0.f);
            u64 accA = z, accB0 = z, accB2 = z, accS1 = z, accS3 = z;
#pragma unroll
            for (int m = 0; m < 21; ++m) {
                u64 ab = AB64[m*73 + j];
                accA = fma2(cs[m], ab, accA);
                int k = m & 3;
                if (k == 0)      accB0 = fma2(cs[m], ab, accB0);
                else if (k == 2) accB2 = fma2(cs[m], ab, accB2);
                else {
                    float2 abf = unpack2(ab);
                    u64 absw = pack2(abf.y, abf.x);
                    if (k == 1) accS1 = fma2(cs[m], absw, accS1);
                    else        accS3 = fma2(cs[m], absw, accS3);
                }
            }
            float2 fa = unpack2(accA);
            pl[j*129 + l] = fa.x - fa.y;
            pl[j*129 + ((128 - l) & 127)] = fa.x + fa.y;
            float2 c0 = unpack2(accB0), c2 = unpack2(accB2);
            float2 s1 = unpack2(accS1), s3 = unpack2(accS3);
            float xb = c0.x - c2.x - s1.y + s3.y;
            float yb = c0.y - c2.y + s1.x - s3.x;
            pl[j*129 + l + 32] = xb - yb;
            pl[j*129 + 96 - l] = xb + yb;
        }
    }
    // row n1=64: alternating sum of A
    for (int j = tid; j < 73; j += 256) {
        float s = 0.f;
#pragma unroll
        for (int m = 0; m < 21; ++m) {
            float a = AB[m*73 + j].x;
            s += (m & 1) ? -a : a;
        }
        pl[j*129 + 64] = s;
    }
    __syncthreads();

    // W-blur (+mask): sliding window per segment, in-place to 65 cols
    {
        int r = tid & 127, seg = tid >> 7;
        float acc[33];
        float win[9];
        if (seg == 0) {
#pragma unroll
            for (int k = 0; k < 9; ++k) {
                int p = k - 4; p = p < 0 ? 0 : p;
                win[k] = pl[p*129 + r];
            }
            for (int j = 0; j < 33; ++j) {
                float a = 0.f;
#pragma unroll
                for (int k = 0; k < 9; ++k) a += GK[k] * win[k];
                acc[j] = a;
#pragma unroll
                for (int k = 0; k < 8; ++k) win[k] = win[k+1];
                win[8] = pl[(j + 5)*129 + r];
            }
        } else {
#pragma unroll
            for (int k = 0; k < 9; ++k)
                win[k] = pl[(37 + k)*129 + r];
            for (int q = 0; q < 32; ++q) {
                float a = 0.f;
#pragma unroll
                for (int k = 0; k < 9; ++k) a += GK[k] * win[k];
                acc[q] = a;
#pragma unroll
                for (int k = 0; k < 8; ++k) win[k] = win[k+1];
                int pn = 46 + q; pn = pn > 72 ? 72 : pn;
                win[8] = pl[pn*129 + r];
            }
        }
        __syncthreads();
        if (seg == 0) {
            for (int j = 0; j < 33; ++j) pl[j*129 + r] = acc[j];
        } else {
            for (int q = 0; q < 32; ++q) pl[(33 + q)*129 + r] = acc[q];
        }
    }
    __syncthreads();

    // H-blur: sliding window along r, store direct to global
    {
        float* out = g_buf1 + (size_t)bo * PS_;
        for (int task = tid; task < 260; task += 256) {
            int seg = task / 65, j = task - seg*65;
            int r0 = seg * 32;
            float win[9];
#pragma unroll
            for (int k = 0; k < 9; ++k) {
                int rr = r0 + k - 4;
                rr = rr < 0 ? 0 : rr;
                win[k] = pl[j*129 + rr];
            }
            for (int q = 0; q < 32; ++q) {
                float a = 0.f;
#pragma unroll
                for (int k = 0; k < 9; ++k) a += GK[k] * win[k];
                out[(r0 + q)*65 + j] = a;
#pragma unroll
                for (int k = 0; k < 8; ++k) win[k] = win[k+1];
                int rn = r0 + q + 5; rn = rn > 127 ? 127 : rn;
                win[8] = pl[j*129 + rn];
            }
        }
    }
}

// K4: zero cols 32..95 of every output row (float4).
__global__ void __launch_bounds__(256) k_zero(float4* __restrict__ out) {
    int idx = blockIdx.x * 256 + threadIdx.x;
    int row = idx >> 4, q = (idx & 15) + 8;
    out[(size_t)row * 32 + q] = make_float4(0.f, 0.f, 0.f, 0.f);
}

// K5: FUSED B-blur + C-blur over [16][64][8-pos] tile; expands to output.
__global__ void __launch_bounds__(256) k_bc(float* __restrict__ out) {
    __shared__ float t[16*520];
    __shared__ int rr8[8], ww8[8];
    int tid = threadIdx.x;
    int p0  = blockIdx.x * 8;

    if (tid < 8) {
        int pos = p0 + tid;
        int r = pos / 65, j = pos - r*65;
        rr8[tid] = r;
        ww8[tid] = (j < 33) ? j : j + 63;
    }
    for (int idx = tid; idx < 8192; idx += 256) {
        int b = idx >> 9, rem = idx & 511;
        int c = rem >> 3, p = rem & 7;
        t[b*520 + rem] = g_buf1[(size_t)b*(CO_*PS_) + (size_t)c*PS_ + p0 + p];
    }
    __syncthreads();

    for (int task = tid; task < 512; task += 256) {
        float v[16], o[16];
#pragma unroll
        for (int b = 0; b < 16; ++b) v[b] = t[b*520 + task];
#pragma unroll
        for (int b = 0; b < 16; ++b) {
            float a = 0.f;
#pragma unroll
            for (int k = 0; k < 9; ++k) {
                int bb = b + k - 4;
                bb = bb < 0 ? 0 : (bb > 15 ? 15 : bb);
                a += GK[k] * v[bb];
            }
            o[b] = a;
        }
#pragma unroll
        for (int b = 0; b < 16; ++b) t[b*520 + task] = o[b];
    }
    __syncthreads();

    float cres[32];
    {
        int b = tid >> 4, p = (tid >> 1) & 7, half = tid & 1;
        const float* line = t + b*520 + p;
        int cbeg = half * 32;
        float win[9];
#pragma unroll
        for (int k = 0; k < 9; ++k) {
            int c = cbeg + k - 4; c = c < 0 ? 0 : (c > 63 ? 63 : c);
            win[k] = line[c*8];
        }
#pragma unroll
        for (int q = 0; q < 32; ++q) {
            float a = 0.f;
#pragma unroll
            for (int k = 0; k < 9; ++k) a += GK[k] * win[k];
            cres[q] = a;
#pragma unroll
            for (int k = 0; k < 8; ++k) win[k] = win[k+1];
            int cn = cbeg + q + 5; cn = cn > 63 ? 63 : cn;
            win[8] = line[cn*8];
        }
    }
    __syncthreads();
    {
        int b = tid >> 4, p = (tid >> 1) & 7, half = tid & 1;
        float* line = t + b*520 + p;
#pragma unroll
        for (int q = 0; q < 32; ++q) line[(half*32 + q)*8] = cres[q];
    }
    __syncthreads();

    for (int idx = tid; idx < 8192; idx += 256) {
        int b = idx >> 9, rem = idx & 511;
        int c = rem >> 3, p = rem & 7;
        out[(size_t)b*(CO_*HW_) + (size_t)c*HW_ + rr8[p]*128 + ww8[p]]
            = t[b*520 + rem];
    }
}

extern "C" void kernel_launch(void* const* d_in, const int* in_sizes, int n_in,
                              void* d_out, int out_size) {
    (void)in_sizes; (void)n_in; (void)out_size;
    const float* x  = (const float*)d_in[0];
    const float* w1 = (const float*)d_in[1];
    float* out = (float*)d_out;

    static bool inited = false;
    static cudaStream_t sW, sZ;
    static cudaEvent_t evFork, evW, evZ;
    if (!inited) {
        cudaStreamCreateWithFlags(&sW, cudaStreamNonBlocking);
        cudaStreamCreateWithFlags(&sZ, cudaStreamNonBlocking);
        cudaEventCreateWithFlags(&evFork, cudaEventDisableTiming);
        cudaEventCreateWithFlags(&evW, cudaEventDisableTiming);
        cudaEventCreateWithFlags(&evZ, cudaEventDisableTiming);
        cudaFuncSetAttribute(k_fwd, cudaFuncAttributeMaxDynamicSharedMemorySize,
                             FW_SMEM);
        cudaFuncSetAttribute(k_invwh, cudaFuncAttributeMaxDynamicSharedMemorySize,
                             IW_SMEM);
        cudaFuncSetAttribute(k_wt, cudaFuncAttributeMaxDynamicSharedMemorySize,
                             WT_SMEM);
        inited = true;
    }

    cudaEventRecord(evFork, 0);
    cudaStreamWaitEvent(sW, evFork, 0);
    cudaStreamWaitEvent(sZ, evFork, 0);

    k_wt<<<128, 256, WT_SMEM, sW>>>(w1);
    cudaEventRecord(evW, sW);

    k_zero<<<(B_*CO_*N_*16)/256, 256, 0, sZ>>>((float4*)out);
    cudaEventRecord(evZ, sZ);

    k_fwd<<<BC_, 320, FW_SMEM>>>(x);
    cudaStreamWaitEvent(0, evW, 0);
    k_mul<<<MODES_*4, 256>>>();
    k_invwh<<<BO_, 256, IW_SMEM>>>();
    cudaStreamWaitEvent(0, evZ, 0);
    k_bc<<<PS_/8, 256>>>(out);
}

// round 17
// speedup vs baseline: 1.0443x; 1.0443x over previous
#include <cuda_runtime.h>
#include <cstddef>

#define B_   16
#define CO_  64
#define N_   128
#define HW_  16384
#define MODES_ 400
#define BC_  1024
#define BO_  1024
#define NC_  73
#define NK_  65
#define PS_  (N_*NK_)      // 8320
#define FW_SMEM  76800     // k_fwd dynamic smem -> 3 blocks/SM
#define IW_SMEM  52640     // k_invwh dynamic smem
#define WT_SMEM  51328     // k_wt dynamic smem

typedef unsigned long long u64;
__device__ __forceinline__ u64 pack2(float lo, float hi) {
    u64 r; asm("mov.b64 %0, {%1,%2};" : "=l"(r) : "f"(lo), "f"(hi)); return r;
}
__device__ __forceinline__ float2 unpack2(u64 v) {
    float2 f; asm("mov.b64 {%0,%1}, %2;" : "=f"(f.x), "=f"(f.y) : "l"(v)); return f;
}
__device__ __forceinline__ u64 fma2(u64 a, u64 b, u64 c) {
    u64 d; asm("fma.rn.f32x2 %0, %1, %2, %3;" : "=l"(d) : "l"(a), "l"(b), "l"(c)); return d;
}

__device__ float  g_Xh[(size_t)MODES_*BC_];    // [mode][bc]
__device__ float  g_Z [(size_t)MODES_*BO_];    // [mode][bo]
__device__ float2 g_W2[(size_t)MODES_*4096];   // [mode][i] = (Wp, Wm)
__device__ float  g_buf1[(size_t)BO_*PS_];

__constant__ float GK[9] = {
    1.3383062e-04f, 4.4318606e-03f, 5.3991128e-02f, 2.4197145e-01f,
    3.9894348e-01f, 2.4197145e-01f, 5.3991128e-02f, 4.4318606e-03f,
    1.3383062e-04f
};

__device__ __forceinline__ void fill_tabs_n(float* ct, float* st, int nthr) {
    const float w = 6.283185307179586f / 128.0f;
    for (int t = threadIdx.x; t < 128; t += nthr) {
        float s, c;
        sincosf(w * (float)t, &s, &c);
        ct[t] = c; st[t] = s;
    }
}

// ---------------------------------------------------------------------------
// K0: transpose + fold weights once: g_W2[m][i] = (0.5(w+wn), 0.5(w-wn))
// ---------------------------------------------------------------------------
__global__ void __launch_bounds__(256) k_wt(const float* __restrict__ w1) {
    extern __shared__ float ws[];            // [32][401]
    int i0 = blockIdx.x * 32;
    for (int idx = threadIdx.x; idx < 32*400; idx += 256) {
        int r = idx / 400, m = idx - r*400;
        ws[r*401 + m] = w1[(size_t)(i0 + r)*400 + m];
    }
    __syncthreads();
    for (int idx = threadIdx.x; idx < 12800; idx += 256) {
        int m = idx >> 5, r = idx & 31;
        int m1 = m / 20, m2 = m - m1*20;
        int mn = ((20 - m1) % 20) * 20 + ((20 - m2) % 20);
        float w  = ws[r*401 + m];
        float wn = ws[r*401 + mn];
        g_W2[(size_t)m*4096 + i0 + r] = make_float2(0.5f*(w+wn), 0.5f*(w-wn));
    }
}

// ---------------------------------------------------------------------------
// K1: forward truncated DHT (packed f32x2), 76.8KB smem -> 3 blocks/SM.
// ---------------------------------------------------------------------------
__global__ void __launch_bounds__(320, 3) k_fwd(const float* __restrict__ x) {
    extern __shared__ float sm[];
    float* CT = sm;             // 64*20
    float* ST = sm + 1280;      // 64*20
    float* xp = sm + 2560;      // 128*65
    float* xm = xp + 8320;      // 128*65
    float* U  = xp;             // overlay after GEMM (2560)
    float* V  = xp + 2560;      // (2560)
    float2* FF = (float2*)(xp + 5120);   // [64][20] pairs
    float2* TT = (float2*)xm;            // [20][65] pairs

    int tid = threadIdx.x;
    int bc  = blockIdx.x;
    const float* xb = x + (size_t)bc * HW_;
    const float wg = 6.283185307179586f / 128.0f;

    for (int idx = tid; idx < 1280; idx += 320) {
        int q = idx / 20, k2 = idx - q*20;
        if (q == 0) { CT[idx] = 1.f; ST[idx] = 0.f; }
        else {
            int t = (q * k2) & 127;
            float s, c; sincosf(wg * (float)t, &s, &c);
            CT[idx] = c; ST[idx] = s;
        }
    }
    for (int idx = tid; idx < 8192; idx += 320) {
        int r = idx >> 6, q = idx & 63;
        const float* row = xb + r * 128;
        if (q == 0) { xp[r*65] = row[0]; xm[r*65] = row[64]; }
        else {
            float a = row[q], b = row[128 - q];
            xp[r*65 + q] = a + b; xm[r*65 + q] = a - b;
        }
    }
    __syncthreads();

    int ty = tid & 31, tx = tid >> 5;
    int isU = (tx < 5);
    int c0  = (isU ? tx : tx - 5) * 4;
    {
        const float* A  = isU ? xp : xm;
        const float* Bm = isU ? CT : ST;
        u64 z = pack2(0.f, 0.f);
        u64 acc01[4] = {z,z,z,z}, acc23[4] = {z,z,z,z};
        float pm[4];
#pragma unroll
        for (int i = 0; i < 4; ++i)
            pm[i] = isU ? xm[(ty + 32*i)*65] : 0.f;
#pragma unroll 4
        for (int q = 0; q < 64; ++q) {
            u64 b01 = *(const u64*)(Bm + q*20 + c0);
            u64 b23 = *(const u64*)(Bm + q*20 + c0 + 2);
#pragma unroll
            for (int i = 0; i < 4; ++i) {
                float a = A[(ty + 32*i)*65 + q];
                u64 aa = pack2(a, a);
                acc01[i] = fma2(aa, b01, acc01[i]);
                acc23[i] = fma2(aa, b23, acc23[i]);
            }
        }
        __syncthreads();
        float* O = isU ? U : V;
#pragma unroll
        for (int i = 0; i < 4; ++i) {
            float2 f01 = unpack2(acc01[i]);
            float2 f23 = unpack2(acc23[i]);
            float* o = O + (ty + 32*i)*20 + c0;
            o[0] = f01.x + pm[i]; o[1] = f01.y - pm[i];
            o[2] = f23.x + pm[i]; o[3] = f23.y - pm[i];
        }
    }
    __syncthreads();

    for (int idx = tid; idx < 1280; idx += 320) {
        int n = idx / 20, k2 = idx - n*20;
        float cd = CT[20 + k2], sd = ST[20 + k2];
        float f1, f2;
        if (n == 0) {
            f1 = U[0*20+k2]  - (sd*U[127*20+k2] + cd*V[127*20+k2]);
            f2 = U[64*20+k2] - (sd*U[63*20+k2]  + cd*V[63*20+k2]);
        } else {
            int nm = n - 1, nn = 128 - n, nnm = 127 - n;
            float e1a = U[n*20+k2]  - (sd*U[nm*20+k2]  + cd*V[nm*20+k2]);
            float e2a = V[n*20+k2]  + (cd*U[nm*20+k2]  - sd*V[nm*20+k2]);
            float e1b = U[nn*20+k2] - (sd*U[nnm*20+k2] + cd*V[nnm*20+k2]);
            float e2b = V[nn*20+k2] + (cd*U[nnm*20+k2] - sd*V[nnm*20+k2]);
            f1 = e1a + e1b;
            f2 = e2a - e2b;
        }
        FF[n*20 + k2] = make_float2(f1, f2);
    }
    for (int idx = tid; idx < 1300; idx += 320) {
        int k1 = idx / 65, n = idx - k1*65;
        if (n == 0) TT[idx] = make_float2(1.f, (k1 & 1) ? -1.f : 1.f);
        else if (n < 64) {
            int t = (k1*n) & 127;
            float s, c; sincosf(wg * (float)t, &s, &c);
            TT[idx] = make_float2(c, -s);
        }
    }
    __syncthreads();

    {
        const u64* TT64 = (const u64*)TT;
        const u64* FF64 = (const u64*)FF;
        for (int o = tid; o < 400; o += 320) {
            int k1 = o % 20, k2 = o / 20;
            u64 acc2 = pack2(0.f, 0.f);
#pragma unroll 8
            for (int n = 0; n < 64; ++n)
                acc2 = fma2(TT64[k1*65 + n], FF64[n*20 + k2], acc2);
            float2 f = unpack2(acc2);
            g_Xh[(size_t)(k1*20 + k2)*BC_ + bc] = f.x + f.y;
        }
    }
}

// ---------------------------------------------------------------------------
// K2: folded compl_mul2d, register-tiled 2b x 2oo (4 outputs/thread):
// 4 LDS.64 feed 4 fma2 -> halves LSU cycles vs 1-output/thread.
// ---------------------------------------------------------------------------
__global__ void __launch_bounds__(256) k_mul(void) {
    __shared__ __align__(16) float X2[2048];   // [b*128 + i*2] = (X, Xneg)
    __shared__ __align__(16) float W2[8192];   // [i*128 + oo*2] = (Wp, Wm)
    int m  = blockIdx.x;
    int m1 = m / 20, m2 = m % 20;
    int mn = ((20 - m1) % 20) * 20 + ((20 - m2) % 20);

    for (int i = threadIdx.x; i < 1024; i += 256) {
        X2[i*2]     = g_Xh[(size_t)m  * BC_ + i];
        X2[i*2 + 1] = g_Xh[(size_t)mn * BC_ + i];
    }
    {
        const float4* src = (const float4*)(g_W2 + (size_t)m*4096);
        float4* dst = (float4*)W2;
#pragma unroll
        for (int k = 0; k < 8; ++k)
            dst[threadIdx.x + 256*k] = src[threadIdx.x + 256*k];
    }
    __syncthreads();

    int bg = threadIdx.x >> 5;      // 0..7
    int og = threadIdx.x & 31;      // 0..31
    const u64* x2a = (const u64*)X2 + bg*64;
    const u64* x2b = (const u64*)X2 + (bg + 8)*64;
    const u64* w2  = (const u64*)W2;
    u64 z = pack2(0.f, 0.f);
    u64 a00 = z, a01 = z, a10 = z, a11 = z;
#pragma unroll 8
    for (int i = 0; i < 64; ++i) {
        u64 xa = x2a[i], xb = x2b[i];
        u64 w0 = w2[i*64 + og];
        u64 w1 = w2[i*64 + og + 32];
        a00 = fma2(xa, w0, a00);
        a01 = fma2(xa, w1, a01);
        a10 = fma2(xb, w0, a10);
        a11 = fma2(xb, w1, a11);
    }
    float* zp = g_Z + (size_t)m * BO_;
    float2 f;
    f = unpack2(a00); zp[bg*64 + og]            = f.x + f.y;
    f = unpack2(a01); zp[bg*64 + og + 32]       = f.x + f.y;
    f = unpack2(a10); zp[(bg + 8)*64 + og]      = f.x + f.y;
    f = unpack2(a11); zp[(bg + 8)*64 + og + 32] = f.x + f.y;
}

// ---------------------------------------------------------------------------
// K3: FUSED inverse transform + W-blur(+mask) + H-blur. One block per (b,o).
// ---------------------------------------------------------------------------
__global__ void __launch_bounds__(256) k_invwh(void) {
    extern __shared__ float sm[];
    float*  ct = sm;
    float*  st = sm + 128;
    float*  Zs = sm + 256;              // [20][21] padded
    float2* AB = (float2*)(sm + 676);   // [21][73] pairs (A,B)
    float*  pl = sm + 3742;             // stride 129, 73 cols
    float*  G1 = pl;
    float*  G2 = pl + 1460;
    float*  P1 = pl + 2920;
    float*  P2 = pl + 4380;

    int tid = threadIdx.x;
    int bo  = blockIdx.x;
    fill_tabs_n(ct, st, 256);
    for (int i = tid; i < 400; i += 256) {
        int m1 = i / 20, m2 = i - m1*20;
        Zs[m1*21 + m2] = g_Z[(size_t)i * BO_ + bo];
    }
    __syncthreads();

    // phase A: m1-register-tiled (4 per thread)
    const float inv = 6.103515625e-05f;
    for (int task = tid; task < 365; task += 256) {
        int j = task / 5, g = task - j*5;
        int m1b = g * 4;
        int n2 = (j < 37) ? j : j + 55;
        float a0=0.f,a1=0.f,a2=0.f,a3=0.f;
        float b0=0.f,b1=0.f,b2=0.f,b3=0.f;
        int t = 0;
#pragma unroll
        for (int m2 = 0; m2 < 20; ++m2) {
            float c = ct[t], s = st[t];
            float z0 = Zs[(m1b+0)*21 + m2];
            float z1 = Zs[(m1b+1)*21 + m2];
            float z2 = Zs[(m1b+2)*21 + m2];
            float z3 = Zs[(m1b+3)*21 + m2];
            a0 += z0*c; b0 += z0*s;
            a1 += z1*c; b1 += z1*s;
            a2 += z2*c; b2 += z2*s;
            a3 += z3*c; b3 += z3*s;
            t = (t + n2) & 127;
        }
        float cb = ct[n2], sb = st[n2];
        float ga[4] = {a0*inv, a1*inv, a2*inv, a3*inv};
        float gb[4] = {b0*inv, b1*inv, b2*inv, b3*inv};
#pragma unroll
        for (int u = 0; u < 4; ++u) {
            int m1 = m1b + u;
            G1[m1*73+j] = ga[u]; G2[m1*73+j] = gb[u];
            P1[m1*73+j] = cb*ga[u] - sb*gb[u];
            P2[m1*73+j] = sb*ga[u] + cb*gb[u];
        }
    }
    __syncthreads();

    for (int idx = tid; idx < 1533; idx += 256) {
        int m = idx / 73, j = idx - m*73;
        float a = 0.f, b = 0.f;
        if (m < 20) { a = G1[m*73+j]; b = G2[m*73+j]; }
        if (m > 0)  { a -= P2[(m-1)*73+j]; b += P1[(m-1)*73+j]; }
        AB[idx] = make_float2(a, b);
    }
    __syncthreads();

    // stage2: one warp per j, lane covers n1=l and n1=l+32
    {
        int l = tid & 31, w = tid >> 5;
        u64 cs[21];
#pragma unroll
        for (int m = 0; m < 21; ++m) {
            int tt = (l * m) & 127;
            cs[m] = pack2(ct[tt], st[tt]);
        }
        const u64* AB64 = (const u64*)AB;
        for (int j = w; j < 73; j += 8) {
            u64 z = pack2(0.f, 0.f);
            u64 accA = z, accB0 = z, accB2 = z, accS1 = z, accS3 = z;
#pragma unroll
            for (int m = 0; m < 21; ++m) {
                u64 ab = AB64[m*73 + j];
                accA = fma2(cs[m], ab, accA);
                int k = m & 3;
                if (k == 0)      accB0 = fma2(cs[m], ab, accB0);
                else if (k == 2) accB2 = fma2(cs[m], ab, accB2);
                else {
                    float2 abf = unpack2(ab);
                    u64 absw = pack2(abf.y, abf.x);
                    if (k == 1) accS1 = fma2(cs[m], absw, accS1);
                    else        accS3 = fma2(cs[m], absw, accS3);
                }
            }
            float2 fa = unpack2(accA);
            pl[j*129 + l] = fa.x - fa.y;
            pl[j*129 + ((128 - l) & 127)] = fa.x + fa.y;
            float2 c0 = unpack2(accB0), c2 = unpack2(accB2);
            float2 s1 = unpack2(accS1), s3 = unpack2(accS3);
            float xb = c0.x - c2.x - s1.y + s3.y;
            float yb = c0.y - c2.y + s1.x - s3.x;
            pl[j*129 + l + 32] = xb - yb;
            pl[j*129 + 96 - l] = xb + yb;
        }
    }
    // row n1=64: alternating sum of A
    for (int j = tid; j < 73; j += 256) {
        float s = 0.f;
#pragma unroll
        for (int m = 0; m < 21; ++m) {
            float a = AB[m*73 + j].x;
            s += (m & 1) ? -a : a;
        }
        pl[j*129 + 64] = s;
    }
    __syncthreads();

    // W-blur (+mask): sliding window per segment, in-place to 65 cols
    {
        int r = tid & 127, seg = tid >> 7;
        float acc[33];
        float win[9];
        if (seg == 0) {
#pragma unroll
            for (int k = 0; k < 9; ++k) {
                int p = k - 4; p = p < 0 ? 0 : p;
                win[k] = pl[p*129 + r];
            }
            for (int j = 0; j < 33; ++j) {
                float a = 0.f;
#pragma unroll
                for (int k = 0; k < 9; ++k) a += GK[k] * win[k];
                acc[j] = a;
#pragma unroll
                for (int k = 0; k < 8; ++k) win[k] = win[k+1];
                win[8] = pl[(j + 5)*129 + r];
            }
        } else {
#pragma unroll
            for (int k = 0; k < 9; ++k)
                win[k] = pl[(37 + k)*129 + r];
            for (int q = 0; q < 32; ++q) {
                float a = 0.f;
#pragma unroll
                for (int k = 0; k < 9; ++k) a += GK[k] * win[k];
                acc[q] = a;
#pragma unroll
                for (int k = 0; k < 8; ++k) win[k] = win[k+1];
                int pn = 46 + q; pn = pn > 72 ? 72 : pn;
                win[8] = pl[pn*129 + r];
            }
        }
        __syncthreads();
        if (seg == 0) {
            for (int j = 0; j < 33; ++j) pl[j*129 + r] = acc[j];
        } else {
            for (int q = 0; q < 32; ++q) pl[(33 + q)*129 + r] = acc[q];
        }
    }
    __syncthreads();

    // H-blur: sliding window along r, store direct to global
    {
        float* out = g_buf1 + (size_t)bo * PS_;
        for (int task = tid; task < 260; task += 256) {
            int seg = task / 65, j = task - seg*65;
            int r0 = seg * 32;
            float win[9];
#pragma unroll
            for (int k = 0; k < 9; ++k) {
                int rr = r0 + k - 4;
                rr = rr < 0 ? 0 : rr;
                win[k] = pl[j*129 + rr];
            }
            for (int q = 0; q < 32; ++q) {
                float a = 0.f;
#pragma unroll
                for (int k = 0; k < 9; ++k) a += GK[k] * win[k];
                out[(r0 + q)*65 + j] = a;
#pragma unroll
                for (int k = 0; k < 8; ++k) win[k] = win[k+1];
                int rn = r0 + q + 5; rn = rn > 127 ? 127 : rn;
                win[8] = pl[j*129 + rn];
            }
        }
    }
}

// K4: zero cols 32..95 of every output row (float4).
__global__ void __launch_bounds__(256) k_zero(float4* __restrict__ out) {
    int idx = blockIdx.x * 256 + threadIdx.x;
    int row = idx >> 4, q = (idx & 15) + 8;
    out[(size_t)row * 32 + q] = make_float4(0.f, 0.f, 0.f, 0.f);
}

// K5: FUSED B-blur + C-blur over [16][64][8-pos] tile; expands to output.
__global__ void __launch_bounds__(256) k_bc(float* __restrict__ out) {
    __shared__ float t[16*520];
    __shared__ int rr8[8], ww8[8];
    int tid = threadIdx.x;
    int p0  = blockIdx.x * 8;

    if (tid < 8) {
        int pos = p0 + tid;
        int r = pos / 65, j = pos - r*65;
        rr8[tid] = r;
        ww8[tid] = (j < 33) ? j : j + 63;
    }
    for (int idx = tid; idx < 8192; idx += 256) {
        int b = idx >> 9, rem = idx & 511;
        int c = rem >> 3, p = rem & 7;
        t[b*520 + rem] = g_buf1[(size_t)b*(CO_*PS_) + (size_t)c*PS_ + p0 + p];
    }
    __syncthreads();

    for (int task = tid; task < 512; task += 256) {
        float v[16], o[16];
#pragma unroll
        for (int b = 0; b < 16; ++b) v[b] = t[b*520 + task];
#pragma unroll
        for (int b = 0; b < 16; ++b) {
            float a = 0.f;
#pragma unroll
            for (int k = 0; k < 9; ++k) {
                int bb = b + k - 4;
                bb = bb < 0 ? 0 : (bb > 15 ? 15 : bb);
                a += GK[k] * v[bb];
            }
            o[b] = a;
        }
#pragma unroll
        for (int b = 0; b < 16; ++b) t[b*520 + task] = o[b];
    }
    __syncthreads();

    float cres[32];
    {
        int b = tid >> 4, p = (tid >> 1) & 7, half = tid & 1;
        const float* line = t + b*520 + p;
        int cbeg = half * 32;
        float win[9];
#pragma unroll
        for (int k = 0; k < 9; ++k) {
            int c = cbeg + k - 4; c = c < 0 ? 0 : (c > 63 ? 63 : c);
            win[k] = line[c*8];
        }
#pragma unroll
        for (int q = 0; q < 32; ++q) {
            float a = 0.f;
#pragma unroll
            for (int k = 0; k < 9; ++k) a += GK[k] * win[k];
            cres[q] = a;
#pragma unroll
            for (int k = 0; k < 8; ++k) win[k] = win[k+1];
            int cn = cbeg + q + 5; cn = cn > 63 ? 63 : cn;
            win[8] = line[cn*8];
        }
    }
    __syncthreads();
    {
        int b = tid >> 4, p = (tid >> 1) & 7, half = tid & 1;
        float* line = t + b*520 + p;
#pragma unroll
        for (int q = 0; q < 32; ++q) line[(half*32 + q)*8] = cres[q];
    }
    __syncthreads();

    for (int idx = tid; idx < 8192; idx += 256) {
        int b = idx >> 9, rem = idx & 511;
        int c = rem >> 3, p = rem & 7;
        out[(size_t)b*(CO_*HW_) + (size_t)c*HW_ + rr8[p]*128 + ww8[p]]
            = t[b*520 + rem];
    }
}

extern "C" void kernel_launch(void* const* d_in, const int* in_sizes, int n_in,
                              void* d_out, int out_size) {
    (void)in_sizes; (void)n_in; (void)out_size;
    const float* x  = (const float*)d_in[0];
    const float* w1 = (const float*)d_in[1];
    float* out = (float*)d_out;

    static bool inited = false;
    static cudaStream_t sW, sZ;
    static cudaEvent_t evFork, evW, evZ;
    if (!inited) {
        cudaStreamCreateWithFlags(&sW, cudaStreamNonBlocking);
        cudaStreamCreateWithFlags(&sZ, cudaStreamNonBlocking);
        cudaEventCreateWithFlags(&evFork, cudaEventDisableTiming);
        cudaEventCreateWithFlags(&evW, cudaEventDisableTiming);
        cudaEventCreateWithFlags(&evZ, cudaEventDisableTiming);
        cudaFuncSetAttribute(k_fwd, cudaFuncAttributeMaxDynamicSharedMemorySize,
                             FW_SMEM);
        cudaFuncSetAttribute(k_invwh, cudaFuncAttributeMaxDynamicSharedMemorySize,
                             IW_SMEM);
        cudaFuncSetAttribute(k_wt, cudaFuncAttributeMaxDynamicSharedMemorySize,
                             WT_SMEM);
        inited = true;
    }

    cudaEventRecord(evFork, 0);
    cudaStreamWaitEvent(sW, evFork, 0);
    cudaStreamWaitEvent(sZ, evFork, 0);

    k_wt<<<128, 256, WT_SMEM, sW>>>(w1);
    cudaEventRecord(evW, sW);

    k_zero<<<(B_*CO_*N_*16)/256, 256, 0, sZ>>>((float4*)out);
    cudaEventRecord(evZ, sZ);

    k_fwd<<<BC_, 320, FW_SMEM>>>(x);
    cudaStreamWaitEvent(0, evW, 0);
    k_mul<<<MODES_, 256>>>();
    k_invwh<<<BO_, 256, IW_SMEM>>>();
    cudaStreamWaitEvent(0, evZ, 0);
    k_bc<<<PS_/8, 256>>>(out);
}